// round 12
// baseline (speedup 1.0000x reference)
#include <cuda_runtime.h>
#include <cuda_bf16.h>
#include <cstdint>

// Problem constants
#define BATCH 8
#define NQ    2048
#define NS    4096
#define DIM   512

// Tiling: BM=64 so TWO CTAs fit per SM (independent pipelines hide each
// other's barrier/drain stalls). 256 threads, 8 warps (2m x 4n, warp 32x32).
// Grid = 8 batches x 32 q-tiles = 256 blocks, all resident.
#define BM 64
#define BN 128
#define BK 64
#define NCHUNK ((NS / BN) * (DIM / BK))   // 32 stiles * 8 kchunks = 256
#define NBUF 3
#define NTHREADS 256

#define A_BYTES    (BM * DIM * 2)              // 65536 = 8 chunks of 8KB
#define BBUF_BYTES (BN * BK * 2)               // 16384
#define RM_OFF     (A_BYTES + NBUF * BBUF_BYTES)   // 114688
#define SMEM_TOTAL (RM_OFF + BM * 4)               // 114944 (~112.2KB, 2/SM)

// Device scratch
__device__ __nv_bfloat16 g_qn[(size_t)BATCH * NQ * DIM];
__device__ __nv_bfloat16 g_sn[(size_t)BATCH * NS * DIM];

// ---------------------------------------------------------------------------
// helpers
// ---------------------------------------------------------------------------
__device__ __forceinline__ uint32_t swz(uint32_t x) {   // SW128: bits[6:4] ^= bits[9:7]
    return x ^ ((x >> 3) & 0x70);
}
__device__ __forceinline__ void cp_async16(uint32_t saddr, const void* gptr) {
    asm volatile("cp.async.cg.shared.global [%0], [%1], 16;\n" :: "r"(saddr), "l"(gptr));
}
__device__ __forceinline__ void cp_commit() {
    asm volatile("cp.async.commit_group;\n" ::: "memory");
}
template <int N>
__device__ __forceinline__ void cp_wait() {
    asm volatile("cp.async.wait_group %0;\n" :: "n"(N) : "memory");
}
__device__ __forceinline__ unsigned fkey(float f) {
    unsigned u = __float_as_uint(f);
    return (u & 0x80000000u) ? ~u : (u | 0x80000000u);
}
__device__ __forceinline__ float funkey(unsigned k) {
    unsigned u = (k & 0x80000000u) ? (k ^ 0x80000000u) : ~k;
    return __uint_as_float(u);
}

// ---------------------------------------------------------------------------
// Normalize: one warp per row of 512 fp32 -> bf16. Also zeroes out[].
// ---------------------------------------------------------------------------
__device__ __forceinline__ void normalize_row(const float* __restrict__ rinF,
                                              __nv_bfloat16* __restrict__ orow, int lane)
{
    const float4* rin = reinterpret_cast<const float4*>(rinF);
    float4 v[4];
    float s = 0.f;
#pragma unroll
    for (int j = 0; j < 4; j++) {
        v[j] = rin[j * 32 + lane];
        s += v[j].x * v[j].x + v[j].y * v[j].y + v[j].z * v[j].z + v[j].w * v[j].w;
    }
#pragma unroll
    for (int o = 16; o > 0; o >>= 1) s += __shfl_xor_sync(0xFFFFFFFFu, s, o);
    float inv = 1.0f / fmaxf(sqrtf(s), 1e-12f);
#pragma unroll
    for (int j = 0; j < 4; j++) {
        __nv_bfloat162 h0 = __floats2bfloat162_rn(v[j].x * inv, v[j].y * inv);
        __nv_bfloat162 h1 = __floats2bfloat162_rn(v[j].z * inv, v[j].w * inv);
        uint2 pk;
        pk.x = *reinterpret_cast<unsigned*>(&h0);
        pk.y = *reinterpret_cast<unsigned*>(&h1);
        *reinterpret_cast<uint2*>(orow + (size_t)(j * 32 + lane) * 4) = pk;
    }
}

__global__ void normalize_all_kernel(const float* __restrict__ q,
                                     const float* __restrict__ s,
                                     float* __restrict__ out)
{
    if (blockIdx.x == 0 && threadIdx.x < BATCH) out[threadIdx.x] = 0.f;
    int row = blockIdx.x * (blockDim.x >> 5) + (threadIdx.x >> 5);
    int lane = threadIdx.x & 31;
    const int nq = BATCH * NQ;
    const int ntot = nq + BATCH * NS;
    if (row >= ntot) return;
    if (row < nq)
        normalize_row(q + (size_t)row * DIM, g_qn + (size_t)row * DIM, lane);
    else {
        int r = row - nq;
        normalize_row(s + (size_t)r * DIM, g_sn + (size_t)r * DIM, lane);
    }
}

// ---------------------------------------------------------------------------
// B chunk fill: chunk ci covers support rows [(ci>>3)*128,+128), k-cols
// [(ci&7)*64,+64). 1024 x 16B segments, 4 per thread (256 threads).
// ---------------------------------------------------------------------------
__device__ __forceinline__ void fill_b_chunk(uint32_t smem_u32,
                                             const __nv_bfloat16* __restrict__ gB,
                                             int ci, int tid)
{
    const int st = ci >> 3;
    const int kc = ci & 7;
    const uint32_t bb = A_BYTES + (uint32_t)(ci % NBUF) * BBUF_BYTES;
#pragma unroll
    for (int i = 0; i < 4; i++) {
        int idx = tid + i * NTHREADS;    // 0..1023
        int r = idx >> 3;                // 8 segs per 128B row
        int s8 = idx & 7;
        const void* src = gB + (size_t)(st * BN + r) * DIM + kc * BK + s8 * 8;
        cp_async16(smem_u32 + bb + swz((uint32_t)(r * 128 + s8 * 16)), src);
    }
    cp_commit();
}

// ---------------------------------------------------------------------------
// GEMM-max: one block per (batch, 64-row q-tile). A (64x512) resident,
// B 3-buffer depth-2 cp.async pipeline. 8 warps, warp tile 32x32.
// Two CTAs co-resident per SM hide each other's stalls.
// ---------------------------------------------------------------------------
__global__ __launch_bounds__(NTHREADS, 2) void gemm_max_kernel(float* __restrict__ out)
{
    extern __shared__ char smem[];
    unsigned* rowmaxU = reinterpret_cast<unsigned*>(smem + RM_OFF);
    __shared__ float red[NTHREADS / 32];
    const uint32_t smem_u32 = (uint32_t)__cvta_generic_to_shared(smem);

    const int b   = blockIdx.x >> 5;     // 32 q-tiles of 64 rows per batch
    const int qt  = blockIdx.x & 31;
    const int tid = threadIdx.x;
    const int lane = tid & 31;
    const int wid  = tid >> 5;
    const int wm = (wid >> 2) * 32;      // 2 m-warps (32 rows each)
    const int wn = (wid & 3) * 32;       // 4 n-warps

    if (tid < BM) rowmaxU[tid] = 0u;

    // ---- A tile: 64 x 512 bf16, 8 swizzled 64-col chunks of 8KB ----
    const __nv_bfloat16* gA = g_qn + (size_t)(b * NQ + qt * BM) * DIM;
#pragma unroll
    for (int i = 0; i < 16; i++) {
        int idx = tid + i * NTHREADS;    // 0..4095 16B segs
        int r = idx >> 6;                // 64 segs per row
        int rest = idx & 63;
        int ch = rest >> 3;
        int s8 = rest & 7;
        const void* src = gA + (size_t)r * DIM + ch * 64 + s8 * 8;
        cp_async16(smem_u32 + ch * 8192 + swz((uint32_t)(r * 128 + s8 * 16)), src);
    }
    cp_commit();

    const __nv_bfloat16* gB = g_sn + (size_t)b * NS * DIM;

    // prologue: chunks 0, 1
    fill_b_chunk(smem_u32, gB, 0, tid);
    fill_b_chunk(smem_u32, gB, 1, tid);

    float C[2][4][4];
#pragma unroll
    for (int mi = 0; mi < 2; mi++)
#pragma unroll
        for (int ni = 0; ni < 4; ni++)
#pragma unroll
            for (int e = 0; e < 4; e++) C[mi][ni][e] = 0.f;

    float rmax[2][2];
#pragma unroll
    for (int mi = 0; mi < 2; mi++) { rmax[mi][0] = -1e30f; rmax[mi][1] = -1e30f; }

    for (int ci = 0; ci < NCHUNK; ci++) {
        if (ci < NCHUNK - 1) cp_wait<1>(); else cp_wait<0>();
        __syncthreads();
        if (ci + 2 < NCHUNK) fill_b_chunk(smem_u32, gB, ci + 2, tid);

        const int kc = ci & 7;           // A chunk index for this k-range
        const uint32_t bb = A_BYTES + (uint32_t)(ci % NBUF) * BBUF_BYTES;

#pragma unroll
        for (int ksp = 0; ksp < 2; ksp++) {
            // B x4 fragments: 2 ksteps per instruction, 4 n-tiles
            unsigned bfr[4][4];
            {
                const uint32_t kb = (uint32_t)(ksp * 64
                                  + ((lane >> 3) & 1) * 16 + (lane >> 4) * 32);
#pragma unroll
                for (int ni = 0; ni < 4; ni++) {
                    int n = wn + ni * 8 + (lane & 7);
                    uint32_t addr = smem_u32 + bb + swz((uint32_t)(n * 128) + kb);
                    asm volatile("ldmatrix.sync.aligned.m8n8.x4.shared.b16 {%0,%1,%2,%3}, [%4];"
                                 : "=r"(bfr[ni][0]), "=r"(bfr[ni][1]),
                                   "=r"(bfr[ni][2]), "=r"(bfr[ni][3])
                                 : "r"(addr));
                }
            }
#pragma unroll
            for (int h = 0; h < 2; h++) {
                const int ks = ksp * 2 + h;
                const uint32_t kb = (uint32_t)(ks * 32 + (lane >> 4) * 16);
                unsigned af[2][4];
#pragma unroll
                for (int mi = 0; mi < 2; mi++) {
                    int r0 = wm + mi * 16 + (lane & 15);
                    uint32_t addr = smem_u32 + kc * 8192
                                  + swz((uint32_t)(r0 * 128) + kb);
                    asm volatile("ldmatrix.sync.aligned.m8n8.x4.shared.b16 {%0,%1,%2,%3}, [%4];"
                                 : "=r"(af[mi][0]), "=r"(af[mi][1]),
                                   "=r"(af[mi][2]), "=r"(af[mi][3])
                                 : "r"(addr));
                }
#pragma unroll
                for (int mi = 0; mi < 2; mi++)
#pragma unroll
                    for (int ni = 0; ni < 4; ni++) {
                        asm volatile(
                            "mma.sync.aligned.m16n8k16.row.col.f32.bf16.bf16.f32 "
                            "{%0,%1,%2,%3}, {%4,%5,%6,%7}, {%8,%9}, {%0,%1,%2,%3};"
                            : "+f"(C[mi][ni][0]), "+f"(C[mi][ni][1]),
                              "+f"(C[mi][ni][2]), "+f"(C[mi][ni][3])
                            : "r"(af[mi][0]), "r"(af[mi][1]),
                              "r"(af[mi][2]), "r"(af[mi][3]),
                              "r"(bfr[ni][2 * h]), "r"(bfr[ni][2 * h + 1]));
                    }
            }
        }

        if (kc == 7) {   // end of s-tile: fold into running row max, reset C
#pragma unroll
            for (int mi = 0; mi < 2; mi++) {
                float m0 = rmax[mi][0], m1 = rmax[mi][1];
#pragma unroll
                for (int ni = 0; ni < 4; ni++) {
                    m0 = fmaxf(m0, fmaxf(C[mi][ni][0], C[mi][ni][1]));
                    m1 = fmaxf(m1, fmaxf(C[mi][ni][2], C[mi][ni][3]));
                    C[mi][ni][0] = 0.f; C[mi][ni][1] = 0.f;
                    C[mi][ni][2] = 0.f; C[mi][ni][3] = 0.f;
                }
                rmax[mi][0] = m0; rmax[mi][1] = m1;
            }
        }
    }

    // epilogue: per-row max across the 4 n-warps via smem atomics
#pragma unroll
    for (int t = 0; t < 2; t++) {
#pragma unroll
        for (int g = 0; g < 2; g++) {
            int row = wm + t * 16 + (lane >> 2) + g * 8;
            atomicMax(&rowmaxU[row], fkey(rmax[t][g]));
        }
    }
    __syncthreads();

    // fused finalize: block owns 64 distinct q-rows with full s-range ->
    // rowmax is final; atomicAdd partial mean into out[b]
    float v = 0.f;
    if (tid < BM) v = 1.0f - funkey(rowmaxU[tid]);
#pragma unroll
    for (int o = 16; o > 0; o >>= 1) v += __shfl_xor_sync(0xFFFFFFFFu, v, o);
    if (lane == 0) red[wid] = v;
    __syncthreads();
    if (wid == 0) {
        float sum = (lane < NTHREADS / 32) ? red[lane] : 0.f;
#pragma unroll
        for (int o = 4; o > 0; o >>= 1) sum += __shfl_xor_sync(0xFFFFFFFFu, sum, o);
        if (lane == 0) atomicAdd(&out[b], sum * (1.0f / NQ));
    }
}

// ---------------------------------------------------------------------------
extern "C" void kernel_launch(void* const* d_in, const int* in_sizes, int n_in,
                              void* d_out, int out_size)
{
    const float* q = (const float*)d_in[0];
    const float* s = (const float*)d_in[1];
    float* out = (float*)d_out;

    cudaFuncSetAttribute(gemm_max_kernel,
                         cudaFuncAttributeMaxDynamicSharedMemorySize, SMEM_TOTAL);

    const int nrows = BATCH * (NQ + NS);
    normalize_all_kernel<<<(nrows + 7) / 8, 256>>>(q, s, out);
    gemm_max_kernel<<<BATCH * (NQ / BM), NTHREADS, SMEM_TOTAL>>>(out);
}

// round 13
// speedup vs baseline: 1.1700x; 1.1700x over previous
#include <cuda_runtime.h>
#include <cuda_bf16.h>
#include <cstdint>

// Problem constants
#define BATCH 8
#define NQ    2048
#define NS    4096
#define DIM   512

// Tiling: 128 blocks (batch x 16 q-tiles of 128). 256 threads, 8 warps in
// 2m x 4n grid, warp tile 64x32. A (128x512) resident/shared. B is
// PER-WARP: each warp triple-buffers its own 32 support rows x K=32 chunk
// (2KB) with its own cp.async groups -> NO barriers in the mainloop.
#define BM 128
#define BN 128                     // s-tile height
#define WNCHUNK ((NS / BN) * (DIM / 32))   // 32 stiles * 16 kchunks = 512
#define NBUF 3
#define NTHREADS 256

#define A_BYTES     (BM * DIM * 2)           // 131072 = 8 chunks of 16KB
#define WBUF_BYTES  2048                     // 32 rows x 64B
#define WREG_BYTES  (NBUF * WBUF_BYTES)      // 6144 per warp
#define RM_OFF      (A_BYTES + 16 * WREG_BYTES)   // wait: 8 warps! fix below
#undef RM_OFF
#define RM_OFF      (A_BYTES + 8 * WREG_BYTES)    // 131072 + 49152 = 180224
#define SMEM_TOTAL  (RM_OFF + BM * 4)             // 180736

// Device scratch
__device__ __nv_bfloat16 g_qn[(size_t)BATCH * NQ * DIM];
__device__ __nv_bfloat16 g_sn[(size_t)BATCH * NS * DIM];

// ---------------------------------------------------------------------------
// helpers
// ---------------------------------------------------------------------------
__device__ __forceinline__ uint32_t swz(uint32_t x) {   // SW128 for A (128B rows)
    return x ^ ((x >> 3) & 0x70);
}
__device__ __forceinline__ void cp_async16(uint32_t saddr, const void* gptr) {
    asm volatile("cp.async.cg.shared.global [%0], [%1], 16;\n" :: "r"(saddr), "l"(gptr));
}
__device__ __forceinline__ void cp_commit() {
    asm volatile("cp.async.commit_group;\n" ::: "memory");
}
template <int N>
__device__ __forceinline__ void cp_wait() {
    asm volatile("cp.async.wait_group %0;\n" :: "n"(N) : "memory");
}
__device__ __forceinline__ unsigned fkey(float f) {
    unsigned u = __float_as_uint(f);
    return (u & 0x80000000u) ? ~u : (u | 0x80000000u);
}
__device__ __forceinline__ float funkey(unsigned k) {
    unsigned u = (k & 0x80000000u) ? (k ^ 0x80000000u) : ~k;
    return __uint_as_float(u);
}

// ---------------------------------------------------------------------------
// Normalize: one warp per row of 512 fp32 -> bf16. Also zeroes out[].
// ---------------------------------------------------------------------------
__device__ __forceinline__ void normalize_row(const float* __restrict__ rinF,
                                              __nv_bfloat16* __restrict__ orow, int lane)
{
    const float4* rin = reinterpret_cast<const float4*>(rinF);
    float4 v[4];
    float s = 0.f;
#pragma unroll
    for (int j = 0; j < 4; j++) {
        v[j] = rin[j * 32 + lane];
        s += v[j].x * v[j].x + v[j].y * v[j].y + v[j].z * v[j].z + v[j].w * v[j].w;
    }
#pragma unroll
    for (int o = 16; o > 0; o >>= 1) s += __shfl_xor_sync(0xFFFFFFFFu, s, o);
    float inv = 1.0f / fmaxf(sqrtf(s), 1e-12f);
#pragma unroll
    for (int j = 0; j < 4; j++) {
        __nv_bfloat162 h0 = __floats2bfloat162_rn(v[j].x * inv, v[j].y * inv);
        __nv_bfloat162 h1 = __floats2bfloat162_rn(v[j].z * inv, v[j].w * inv);
        uint2 pk;
        pk.x = *reinterpret_cast<unsigned*>(&h0);
        pk.y = *reinterpret_cast<unsigned*>(&h1);
        *reinterpret_cast<uint2*>(orow + (size_t)(j * 32 + lane) * 4) = pk;
    }
}

__global__ void normalize_all_kernel(const float* __restrict__ q,
                                     const float* __restrict__ s,
                                     float* __restrict__ out)
{
    if (blockIdx.x == 0 && threadIdx.x < BATCH) out[threadIdx.x] = 0.f;
    int row = blockIdx.x * (blockDim.x >> 5) + (threadIdx.x >> 5);
    int lane = threadIdx.x & 31;
    const int nq = BATCH * NQ;
    const int ntot = nq + BATCH * NS;
    if (row >= ntot) return;
    if (row < nq)
        normalize_row(q + (size_t)row * DIM, g_qn + (size_t)row * DIM, lane);
    else {
        int r = row - nq;
        normalize_row(s + (size_t)r * DIM, g_sn + (size_t)r * DIM, lane);
    }
}

// ---------------------------------------------------------------------------
// Per-warp B chunk fill: chunk ci = st*16 + kc covers this warp's support
// rows [st*128 + wn, +32), k-cols [kc*32, +32) (64B). 128 segs, 4 per lane.
// 64B rows with conflict-free swizzle: 16B-col c -> c ^ ((row>>1)&3).
// ---------------------------------------------------------------------------
__device__ __forceinline__ void fill_b_warp(uint32_t wreg, 
                                            const __nv_bfloat16* __restrict__ gB,
                                            int ci, int wn, int lane)
{
    const int st = ci >> 4;
    const int kc = ci & 15;
    const uint32_t wb = wreg + (uint32_t)(ci % NBUF) * WBUF_BYTES;
#pragma unroll
    for (int j = 0; j < 4; j++) {
        int idx = lane + j * 32;         // 0..127
        int r = idx >> 2;                // local row 0..31
        int s8 = idx & 3;                // 16B col 0..3
        const void* src = gB + (size_t)(st * BN + wn + r) * DIM + kc * 32 + s8 * 8;
        uint32_t dst = wb + (uint32_t)(r * 64 + ((s8 ^ ((r >> 1) & 3)) << 4));
        cp_async16(dst, src);
    }
    cp_commit();
}

// ---------------------------------------------------------------------------
// GEMM-max: barrier-free mainloop. Each warp owns its B pipeline; A is
// resident and read-only after one startup barrier.
// ---------------------------------------------------------------------------
__global__ __launch_bounds__(NTHREADS, 1) void gemm_max_kernel(float* __restrict__ out)
{
    extern __shared__ char smem[];
    unsigned* rowmaxU = reinterpret_cast<unsigned*>(smem + RM_OFF);
    __shared__ float red[NTHREADS / 32];
    const uint32_t smem_u32 = (uint32_t)__cvta_generic_to_shared(smem);

    const int b   = blockIdx.x >> 4;
    const int qt  = blockIdx.x & 15;
    const int tid = threadIdx.x;
    const int lane = tid & 31;
    const int wid  = tid >> 5;
    const int wm = (wid >> 2) * 64;      // 2 m-warps
    const int wn = (wid & 3) * 32;       // 4 n-warps (each owns 32 B rows)
    const uint32_t wreg = smem_u32 + A_BYTES + (uint32_t)wid * WREG_BYTES;

    // ---- A tile: 128 x 512 bf16, 8 swizzled 16KB chunks (all threads) ----
    const __nv_bfloat16* gA = g_qn + (size_t)(b * NQ + qt * BM) * DIM;
#pragma unroll
    for (int i = 0; i < 32; i++) {
        int idx = tid + i * NTHREADS;    // 0..8191 16B segs
        int r = idx >> 6;
        int rest = idx & 63;
        int ch = rest >> 3;
        int s8 = rest & 7;
        const void* src = gA + (size_t)r * DIM + ch * 64 + s8 * 8;
        cp_async16(smem_u32 + ch * 16384 + swz((uint32_t)(r * 128 + s8 * 16)), src);
    }
    cp_commit();

    const __nv_bfloat16* gB = g_sn + (size_t)b * NS * DIM;

    // per-warp prologue: chunks 0, 1
    fill_b_warp(wreg, gB, 0, wn, lane);
    fill_b_warp(wreg, gB, 1, wn, lane);

    cp_wait<2>();                        // A (oldest group) complete
    if (tid < BM) rowmaxU[tid] = 0u;
    __syncthreads();                     // the ONLY block barrier before epilogue

    float C[4][4][4];
#pragma unroll
    for (int mi = 0; mi < 4; mi++)
#pragma unroll
        for (int ni = 0; ni < 4; ni++)
#pragma unroll
            for (int e = 0; e < 4; e++) C[mi][ni][e] = 0.f;

    float rmax[4][2];
#pragma unroll
    for (int t = 0; t < 4; t++) { rmax[t][0] = -1e30f; rmax[t][1] = -1e30f; }

    for (int ci = 0; ci < WNCHUNK; ci++) {
        if (ci < WNCHUNK - 1) cp_wait<1>(); else cp_wait<0>();
        if (ci + 2 < WNCHUNK) fill_b_warp(wreg, gB, ci + 2, wn, lane);

        const int kc = ci & 15;          // k-chunk within s-tile (K=32)
        const uint32_t wb = wreg + (uint32_t)(ci % NBUF) * WBUF_BYTES;

        // B fragments: 4 x4 loads cover n 0..31 for both ksteps of this chunk
        unsigned bfr[4][4];
        {
            const int s = lane >> 3;     // 16B col 0..3 (k bytes s*16)
#pragma unroll
            for (int ni = 0; ni < 4; ni++) {
                int n = ni * 8 + (lane & 7);
                uint32_t addr = wb + (uint32_t)(n * 64 + ((s ^ ((n >> 1) & 3)) << 4));
                asm volatile("ldmatrix.sync.aligned.m8n8.x4.shared.b16 {%0,%1,%2,%3}, [%4];"
                             : "=r"(bfr[ni][0]), "=r"(bfr[ni][1]),
                               "=r"(bfr[ni][2]), "=r"(bfr[ni][3])
                             : "r"(addr));
            }
        }
#pragma unroll
        for (int h = 0; h < 2; h++) {
            const int gk = kc * 2 + h;   // global kstep 0..31
            const int ach = gk >> 2;     // A 16KB chunk
            const uint32_t kb = (uint32_t)((gk & 3) * 32 + (lane >> 4) * 16);
            unsigned af[4][4];
#pragma unroll
            for (int mi = 0; mi < 4; mi++) {
                int r0 = wm + mi * 16 + (lane & 15);
                uint32_t addr = smem_u32 + ach * 16384
                              + swz((uint32_t)(r0 * 128) + kb);
                asm volatile("ldmatrix.sync.aligned.m8n8.x4.shared.b16 {%0,%1,%2,%3}, [%4];"
                             : "=r"(af[mi][0]), "=r"(af[mi][1]),
                               "=r"(af[mi][2]), "=r"(af[mi][3])
                             : "r"(addr));
            }
#pragma unroll
            for (int mi = 0; mi < 4; mi++)
#pragma unroll
                for (int ni = 0; ni < 4; ni++) {
                    asm volatile(
                        "mma.sync.aligned.m16n8k16.row.col.f32.bf16.bf16.f32 "
                        "{%0,%1,%2,%3}, {%4,%5,%6,%7}, {%8,%9}, {%0,%1,%2,%3};"
                        : "+f"(C[mi][ni][0]), "+f"(C[mi][ni][1]),
                          "+f"(C[mi][ni][2]), "+f"(C[mi][ni][3])
                        : "r"(af[mi][0]), "r"(af[mi][1]),
                          "r"(af[mi][2]), "r"(af[mi][3]),
                        "r"(bfr[ni][2 * h]), "r"(bfr[ni][2 * h + 1]));
                }
        }

        if (kc == 15) {  // end of s-tile: fold into running row max, reset C
#pragma unroll
            for (int mi = 0; mi < 4; mi++) {
                float m0 = rmax[mi][0], m1 = rmax[mi][1];
#pragma unroll
                for (int ni = 0; ni < 4; ni++) {
                    m0 = fmaxf(m0, fmaxf(C[mi][ni][0], C[mi][ni][1]));
                    m1 = fmaxf(m1, fmaxf(C[mi][ni][2], C[mi][ni][3]));
                    C[mi][ni][0] = 0.f; C[mi][ni][1] = 0.f;
                    C[mi][ni][2] = 0.f; C[mi][ni][3] = 0.f;
                }
                rmax[mi][0] = m0; rmax[mi][1] = m1;
            }
        }
    }

    // epilogue: per-row max across warps via smem atomics
#pragma unroll
    for (int t = 0; t < 4; t++) {
#pragma unroll
        for (int g = 0; g < 2; g++) {
            int row = wm + t * 16 + (lane >> 2) + g * 8;
            atomicMax(&rowmaxU[row], fkey(rmax[t][g]));
        }
    }
    __syncthreads();

    // fused finalize: block sum of (1 - rowmax) -> atomicAdd(out[b], sum/NQ)
    float v = 0.f;
    if (tid < BM) v = 1.0f - funkey(rowmaxU[tid]);
#pragma unroll
    for (int o = 16; o > 0; o >>= 1) v += __shfl_xor_sync(0xFFFFFFFFu, v, o);
    if (lane == 0) red[wid] = v;
    __syncthreads();
    if (wid == 0) {
        float sum = (lane < NTHREADS / 32) ? red[lane] : 0.f;
#pragma unroll
        for (int o = 4; o > 0; o >>= 1) sum += __shfl_xor_sync(0xFFFFFFFFu, sum, o);
        if (lane == 0) atomicAdd(&out[b], sum * (1.0f / NQ));
    }
}

// ---------------------------------------------------------------------------
extern "C" void kernel_launch(void* const* d_in, const int* in_sizes, int n_in,
                              void* d_out, int out_size)
{
    const float* q = (const float*)d_in[0];
    const float* s = (const float*)d_in[1];
    float* out = (float*)d_out;

    cudaFuncSetAttribute(gemm_max_kernel,
                         cudaFuncAttributeMaxDynamicSharedMemorySize, SMEM_TOTAL);

    const int nrows = BATCH * (NQ + NS);
    normalize_all_kernel<<<(nrows + 7) / 8, 256>>>(q, s, out);
    gemm_max_kernel<<<BATCH * (NQ / BM), NTHREADS, SMEM_TOTAL>>>(out);
}

// round 14
// speedup vs baseline: 1.2897x; 1.1024x over previous
#include <cuda_runtime.h>
#include <cuda_bf16.h>
#include <cstdint>

// Problem constants
#define BATCH 8
#define NQ    2048
#define NS    4096
#define DIM   512

// Tiling: two independent 256-thread groups per CTA (own named barrier, own
// B ring), group g handles s-tiles g, g+2, ... A (128x512 bf16) resident,
// normalized IN-KERNEL from fp32 query (no global bf16 round-trip for A).
#define BM 128
#define BN 128
#define BK 64
#define GCHUNK 128
#define NBUF 3
#define NTHREADS 512

#define A_BYTES    (BM * DIM * 2)              // 131072 = 8 chunks of 16KB
#define BBUF_BYTES (BN * BK * 2)               // 16384
#define RM_OFF     (A_BYTES + 2 * NBUF * BBUF_BYTES)   // 229376
#define SMEM_TOTAL (RM_OFF + BM * 4)                   // 229888

// Device scratch (support only; query is normalized inside the GEMM)
__device__ __nv_bfloat16 g_sn[(size_t)BATCH * NS * DIM];

// ---------------------------------------------------------------------------
// helpers
// ---------------------------------------------------------------------------
__device__ __forceinline__ uint32_t swz(uint32_t x) {   // SW128: bits[6:4] ^= bits[9:7]
    return x ^ ((x >> 3) & 0x70);
}
__device__ __forceinline__ void cp_async16(uint32_t saddr, const void* gptr) {
    asm volatile("cp.async.cg.shared.global [%0], [%1], 16;\n" :: "r"(saddr), "l"(gptr));
}
__device__ __forceinline__ void cp_commit() {
    asm volatile("cp.async.commit_group;\n" ::: "memory");
}
template <int N>
__device__ __forceinline__ void cp_wait() {
    asm volatile("cp.async.wait_group %0;\n" :: "n"(N) : "memory");
}
__device__ __forceinline__ void bar_g(int id) {
    asm volatile("bar.sync %0, 256;" :: "r"(id) : "memory");
}
__device__ __forceinline__ unsigned fkey(float f) {
    unsigned u = __float_as_uint(f);
    return (u & 0x80000000u) ? ~u : (u | 0x80000000u);
}
__device__ __forceinline__ float funkey(unsigned k) {
    unsigned u = (k & 0x80000000u) ? (k ^ 0x80000000u) : ~k;
    return __uint_as_float(u);
}

// ---------------------------------------------------------------------------
// Support normalize: one warp per row of 512 fp32 -> bf16. Also zeroes out[].
// ---------------------------------------------------------------------------
__global__ void normalize_s_kernel(const float* __restrict__ s,
                                   float* __restrict__ out)
{
    if (blockIdx.x == 0 && threadIdx.x < BATCH) out[threadIdx.x] = 0.f;
    int row = blockIdx.x * (blockDim.x >> 5) + (threadIdx.x >> 5);
    int lane = threadIdx.x & 31;
    if (row >= BATCH * NS) return;

    const float4* rin = reinterpret_cast<const float4*>(s + (size_t)row * DIM);
    float4 v[4];
    float acc = 0.f;
#pragma unroll
    for (int j = 0; j < 4; j++) {
        v[j] = rin[j * 32 + lane];
        acc += v[j].x * v[j].x + v[j].y * v[j].y + v[j].z * v[j].z + v[j].w * v[j].w;
    }
#pragma unroll
    for (int o = 16; o > 0; o >>= 1) acc += __shfl_xor_sync(0xFFFFFFFFu, acc, o);
    float inv = 1.0f / fmaxf(sqrtf(acc), 1e-12f);

    __nv_bfloat16* orow = g_sn + (size_t)row * DIM;
#pragma unroll
    for (int j = 0; j < 4; j++) {
        __nv_bfloat162 h0 = __floats2bfloat162_rn(v[j].x * inv, v[j].y * inv);
        __nv_bfloat162 h1 = __floats2bfloat162_rn(v[j].z * inv, v[j].w * inv);
        uint2 pk;
        pk.x = *reinterpret_cast<unsigned*>(&h0);
        pk.y = *reinterpret_cast<unsigned*>(&h1);
        *reinterpret_cast<uint2*>(orow + (size_t)(j * 32 + lane) * 4) = pk;
    }
}

// ---------------------------------------------------------------------------
// B chunk fill (per group): local chunk ci -> s-tile (2*(ci>>3)+gid),
// k-cols [(ci&7)*64, +64). 1024 x 16B segments, 4 per group-thread.
// ---------------------------------------------------------------------------
__device__ __forceinline__ void fill_b_chunk(uint32_t smem_u32,
                                             const __nv_bfloat16* __restrict__ gB,
                                             int ci, int gid, int gtid)
{
    const int st = 2 * (ci >> 3) + gid;
    const int kc = ci & 7;
    const uint32_t bb = A_BYTES
                      + (uint32_t)(gid * NBUF + (ci % NBUF)) * BBUF_BYTES;
#pragma unroll
    for (int i = 0; i < 4; i++) {
        int idx = gtid + i * 256;        // 0..1023
        int r = idx >> 3;                // 8 segs per 128B row
        int s8 = idx & 7;
        const void* src = gB + (size_t)(st * BN + r) * DIM + kc * BK + s8 * 8;
        cp_async16(smem_u32 + bb + swz((uint32_t)(r * 128 + s8 * 16)), src);
    }
    cp_commit();
}

// ---------------------------------------------------------------------------
// GEMM-max: one block per (batch, q-tile), 512 threads = 2 independent
// 256-thread pipelines. A normalized in-prologue from fp32 query.
// ---------------------------------------------------------------------------
__global__ __launch_bounds__(NTHREADS, 1) void gemm_max_kernel(
    const float* __restrict__ qf, float* __restrict__ out)
{
    extern __shared__ char smem[];
    unsigned* rowmaxU = reinterpret_cast<unsigned*>(smem + RM_OFF);
    __shared__ float red[NTHREADS / 32];
    const uint32_t smem_u32 = (uint32_t)__cvta_generic_to_shared(smem);

    const int b   = blockIdx.x >> 4;
    const int qt  = blockIdx.x & 15;
    const int tid = threadIdx.x;
    const int lane = tid & 31;
    const int wid  = tid >> 5;
    const int gid  = wid >> 3;           // warp-group 0 / 1
    const int gtid = tid & 255;
    const int gwid = wid & 7;
    const int wm = (gwid >> 2) * 64;
    const int wn = (gwid & 3) * 32;

    if (tid < BM) rowmaxU[tid] = 0u;

    const __nv_bfloat16* gB = g_sn + (size_t)b * NS * DIM;

    // group prologue: own chunks 0, 1 (issue fills first — mainloop deadline)
    fill_b_chunk(smem_u32, gB, 0, gid, gtid);
    fill_b_chunk(smem_u32, gB, 1, gid, gtid);

    // ---- A tile: normalize 128 q-rows fp32 -> bf16 straight into swizzled
    //      smem. 16 warps x 8 rows; lane owns cols [16*lane, +16). ----
    {
        const float* gQ = qf + (size_t)(b * NQ + qt * BM) * DIM;
        const int ch = lane >> 2;            // 64-col chunk 0..7
        const int s8 = (lane & 3) * 2;       // first 16B seg within chunk
#pragma unroll
        for (int rr = 0; rr < 8; rr++) {
            int r = wid * 8 + rr;
            const float4* rin = reinterpret_cast<const float4*>(gQ + (size_t)r * DIM);
            float4 v[4];
            float acc = 0.f;
#pragma unroll
            for (int j = 0; j < 4; j++) {
                v[j] = rin[lane * 4 + j];    // cols 16*lane + 4j .. +3
                acc += v[j].x * v[j].x + v[j].y * v[j].y
                     + v[j].z * v[j].z + v[j].w * v[j].w;
            }
#pragma unroll
            for (int o = 16; o > 0; o >>= 1)
                acc += __shfl_xor_sync(0xFFFFFFFFu, acc, o);
            float inv = 1.0f / fmaxf(sqrtf(acc), 1e-12f);

            unsigned pk[8];
#pragma unroll
            for (int j = 0; j < 4; j++) {
                __nv_bfloat162 h0 = __floats2bfloat162_rn(v[j].x * inv, v[j].y * inv);
                __nv_bfloat162 h1 = __floats2bfloat162_rn(v[j].z * inv, v[j].w * inv);
                pk[2 * j]     = *reinterpret_cast<unsigned*>(&h0);
                pk[2 * j + 1] = *reinterpret_cast<unsigned*>(&h1);
            }
            uint4 q0 = make_uint4(pk[0], pk[1], pk[2], pk[3]);
            uint4 q1 = make_uint4(pk[4], pk[5], pk[6], pk[7]);
            *reinterpret_cast<uint4*>(smem + ch * 16384
                + swz((uint32_t)(r * 128 + s8 * 16))) = q0;
            *reinterpret_cast<uint4*>(smem + ch * 16384
                + swz((uint32_t)(r * 128 + (s8 + 1) * 16))) = q1;
        }
    }
    __syncthreads();                     // A + rowmax init visible to all

    float C[4][4][4];
#pragma unroll
    for (int mi = 0; mi < 4; mi++)
#pragma unroll
        for (int ni = 0; ni < 4; ni++)
#pragma unroll
            for (int e = 0; e < 4; e++) C[mi][ni][e] = 0.f;

    float rmax[4][2];
#pragma unroll
    for (int t = 0; t < 4; t++) { rmax[t][0] = -1e30f; rmax[t][1] = -1e30f; }

    for (int ci = 0; ci < GCHUNK; ci++) {
        if (ci < GCHUNK - 1) cp_wait<1>(); else cp_wait<0>();
        bar_g(1 + gid);
        if (ci + 2 < GCHUNK) fill_b_chunk(smem_u32, gB, ci + 2, gid, gtid);

        const int kc = ci & 7;           // A chunk index for this k-range
        const uint32_t bb = A_BYTES
                          + (uint32_t)(gid * NBUF + (ci % NBUF)) * BBUF_BYTES;

#pragma unroll
        for (int ksp = 0; ksp < 2; ksp++) {
            unsigned bfr[4][4];
            {
                const uint32_t kb = (uint32_t)(ksp * 64
                                  + ((lane >> 3) & 1) * 16 + (lane >> 4) * 32);
#pragma unroll
                for (int ni = 0; ni < 4; ni++) {
                    int n = wn + ni * 8 + (lane & 7);
                    uint32_t addr = smem_u32 + bb + swz((uint32_t)(n * 128) + kb);
                    asm volatile("ldmatrix.sync.aligned.m8n8.x4.shared.b16 {%0,%1,%2,%3}, [%4];"
                                 : "=r"(bfr[ni][0]), "=r"(bfr[ni][1]),
                                   "=r"(bfr[ni][2]), "=r"(bfr[ni][3])
                                 : "r"(addr));
                }
            }
#pragma unroll
            for (int h = 0; h < 2; h++) {
                const int ks = ksp * 2 + h;
                const uint32_t kb = (uint32_t)(ks * 32 + (lane >> 4) * 16);
                unsigned af[4][4];
#pragma unroll
                for (int mi = 0; mi < 4; mi++) {
                    int r0 = wm + mi * 16 + (lane & 15);
                    uint32_t addr = smem_u32 + kc * 16384
                                  + swz((uint32_t)(r0 * 128) + kb);
                    asm volatile("ldmatrix.sync.aligned.m8n8.x4.shared.b16 {%0,%1,%2,%3}, [%4];"
                                 : "=r"(af[mi][0]), "=r"(af[mi][1]),
                                   "=r"(af[mi][2]), "=r"(af[mi][3])
                                 : "r"(addr));
                }
#pragma unroll
                for (int mi = 0; mi < 4; mi++)
#pragma unroll
                    for (int ni = 0; ni < 4; ni++) {
                        asm volatile(
                            "mma.sync.aligned.m16n8k16.row.col.f32.bf16.bf16.f32 "
                            "{%0,%1,%2,%3}, {%4,%5,%6,%7}, {%8,%9}, {%0,%1,%2,%3};"
                            : "+f"(C[mi][ni][0]), "+f"(C[mi][ni][1]),
                              "+f"(C[mi][ni][2]), "+f"(C[mi][ni][3])
                            : "r"(af[mi][0]), "r"(af[mi][1]),
                              "r"(af[mi][2]), "r"(af[mi][3]),
                              "r"(bfr[ni][2 * h]), "r"(bfr[ni][2 * h + 1]));
                    }
            }
        }

        if (kc == 7) {   // end of s-tile: fold into running row max, reset C
#pragma unroll
            for (int mi = 0; mi < 4; mi++) {
                float m0 = rmax[mi][0], m1 = rmax[mi][1];
#pragma unroll
                for (int ni = 0; ni < 4; ni++) {
                    m0 = fmaxf(m0, fmaxf(C[mi][ni][0], C[mi][ni][1]));
                    m1 = fmaxf(m1, fmaxf(C[mi][ni][2], C[mi][ni][3]));
                    C[mi][ni][0] = 0.f; C[mi][ni][1] = 0.f;
                    C[mi][ni][2] = 0.f; C[mi][ni][3] = 0.f;
                }
                rmax[mi][0] = m0; rmax[mi][1] = m1;
            }
        }
    }

    // epilogue: per-row max across warps/groups via smem atomics
#pragma unroll
    for (int t = 0; t < 4; t++) {
#pragma unroll
        for (int g = 0; g < 2; g++) {
            int row = wm + t * 16 + (lane >> 2) + g * 8;
            atomicMax(&rowmaxU[row], fkey(rmax[t][g]));
        }
    }
    __syncthreads();

    // fused finalize: block sum of (1 - rowmax) -> atomicAdd(out[b], sum/NQ)
    float v = 0.f;
    if (tid < BM) v = 1.0f - funkey(rowmaxU[tid]);
#pragma unroll
    for (int o = 16; o > 0; o >>= 1) v += __shfl_xor_sync(0xFFFFFFFFu, v, o);
    if (lane == 0) red[wid] = v;
    __syncthreads();
    if (wid == 0) {
        float sum = (lane < NTHREADS / 32) ? red[lane] : 0.f;
#pragma unroll
        for (int o = 8; o > 0; o >>= 1) sum += __shfl_xor_sync(0xFFFFFFFFu, sum, o);
        if (lane == 0) atomicAdd(&out[b], sum * (1.0f / NQ));
    }
}

// ---------------------------------------------------------------------------
extern "C" void kernel_launch(void* const* d_in, const int* in_sizes, int n_in,
                              void* d_out, int out_size)
{
    const float* q = (const float*)d_in[0];
    const float* s = (const float*)d_in[1];
    float* out = (float*)d_out;

    cudaFuncSetAttribute(gemm_max_kernel,
                         cudaFuncAttributeMaxDynamicSharedMemorySize, SMEM_TOTAL);

    normalize_s_kernel<<<(BATCH * NS + 7) / 8, 256>>>(s, out);
    gemm_max_kernel<<<BATCH * (NQ / BM), NTHREADS, SMEM_TOTAL>>>(q, out);
}